// round 1
// baseline (speedup 1.0000x reference)
#include <cuda_runtime.h>
#include <cuda_bf16.h>
#include <math_constants.h>

// ---------------- problem constants ----------------
#define B_    2
#define S_    2048
#define DIM_  2048
#define NH_   16
#define DQK_  192
#define DNOPE_ 128
#define DROPE_ 64
#define DV_   128
#define RANK_ 512
#define M_    (B_*S_)          // 4096 rows total
#define NQ_   (NH_*DQK_)       // 3072
#define NKV_  (RANK_+DROPE_)   // 576
#define NUP_  (NH_*(DNOPE_+DV_)) // 4096
#define NO_   (NH_*DV_)        // 2048

// ---------------- scratch (device globals; no allocs allowed) ----------------
__device__ float g_q   [M_ * NQ_];    // 50.3 MB  q (roped in place)
__device__ float g_kv  [M_ * NKV_];   //  9.4 MB  x @ wkv_a^T
__device__ float g_kvn [M_ * RANK_];  //  8.4 MB  rmsnorm(kv_lat)
__device__ float g_kpe [M_ * DROPE_]; //  1.0 MB  roped k_pe
__device__ float g_kvup[M_ * NUP_];   // 67.1 MB  kvnorm @ wkv_b^T
__device__ float g_attn[M_ * NO_];    // 33.5 MB  attention output

// ---------------- SGEMM: C[M,N] = A[M,K] * W[N,K]^T ----------------
// 128x128 tile, BK=8, 256 threads, 8x8 per thread. M,K assumed multiples of 128/8.
__device__ __forceinline__ void gemm_body(const float* __restrict__ A,
                                          const float* __restrict__ W,
                                          float* __restrict__ C,
                                          int M, int N, int K)
{
    __shared__ float As[8][132];
    __shared__ float Ws[8][132];
    const int tid = threadIdx.x;
    const int m0 = blockIdx.y * 128;
    const int n0 = blockIdx.x * 128;
    const int lr = tid >> 1;          // 0..127
    const int lc = (tid & 1) * 4;     // 0 or 4
    const int tr = (tid >> 4) * 8;    // row within tile
    const int tc = (tid & 15) * 8;    // col within tile

    float acc[8][8];
#pragma unroll
    for (int i = 0; i < 8; i++)
#pragma unroll
        for (int j = 0; j < 8; j++) acc[i][j] = 0.f;

    const float* Aptr = A + (size_t)(m0 + lr) * K + lc;
    const bool wok = (n0 + lr) < N;
    const float* Wptr = W + (size_t)(n0 + lr) * K + lc;

    for (int k0 = 0; k0 < K; k0 += 8) {
        float4 av = *(const float4*)(Aptr + k0);
        float4 wv = wok ? *(const float4*)(Wptr + k0) : make_float4(0.f,0.f,0.f,0.f);
        As[lc+0][lr] = av.x; As[lc+1][lr] = av.y; As[lc+2][lr] = av.z; As[lc+3][lr] = av.w;
        Ws[lc+0][lr] = wv.x; Ws[lc+1][lr] = wv.y; Ws[lc+2][lr] = wv.z; Ws[lc+3][lr] = wv.w;
        __syncthreads();
#pragma unroll
        for (int kk = 0; kk < 8; kk++) {
            float ra[8], rb[8];
            *(float4*)&ra[0] = *(const float4*)&As[kk][tr];
            *(float4*)&ra[4] = *(const float4*)&As[kk][tr+4];
            *(float4*)&rb[0] = *(const float4*)&Ws[kk][tc];
            *(float4*)&rb[4] = *(const float4*)&Ws[kk][tc+4];
#pragma unroll
            for (int i = 0; i < 8; i++)
#pragma unroll
                for (int j = 0; j < 8; j++)
                    acc[i][j] = fmaf(ra[i], rb[j], acc[i][j]);
        }
        __syncthreads();
    }

#pragma unroll
    for (int i = 0; i < 8; i++) {
#pragma unroll
        for (int j = 0; j < 8; j++) {
            int n = n0 + tc + j;
            if (n < N) C[(size_t)(m0 + tr + i) * N + n] = acc[i][j];
        }
    }
}

__global__ void __launch_bounds__(256) k_gemm_q(const float* __restrict__ x,
                                                const float* __restrict__ wq)
{ gemm_body(x, wq, g_q, M_, NQ_, DIM_); }

__global__ void __launch_bounds__(256) k_gemm_kv(const float* __restrict__ x,
                                                 const float* __restrict__ wa)
{ gemm_body(x, wa, g_kv, M_, NKV_, DIM_); }

__global__ void __launch_bounds__(256) k_gemm_kvup(const float* __restrict__ wb)
{ gemm_body(g_kvn, wb, g_kvup, M_, NUP_, RANK_); }

__global__ void __launch_bounds__(256) k_gemm_o(const float* __restrict__ wo,
                                                float* __restrict__ out)
{ gemm_body(g_attn, wo, out, M_, DIM_, NO_); }

// ---------------- fused elementwise: rmsnorm + both RoPEs ----------------
// grid = M_, 256 threads. freqs_cis layout [S, 32, 2] (cos, sin).
__global__ void __launch_bounds__(256) k_ew(const float* __restrict__ fc,
                                            const float* __restrict__ knw)
{
    __shared__ float red[8];
    __shared__ float rsv;
    const int m   = blockIdx.x;
    const int s   = m & (S_ - 1);
    const int tid = threadIdx.x;
    const float* kvrow = g_kv + (size_t)m * NKV_;

    // sum of squares over kv_lat[0:512]
    float v0 = kvrow[tid];
    float v1 = kvrow[tid + 256];
    float ss = v0 * v0 + v1 * v1;
#pragma unroll
    for (int o = 16; o; o >>= 1) ss += __shfl_xor_sync(0xffffffffu, ss, o);
    if ((tid & 31) == 0) red[tid >> 5] = ss;
    __syncthreads();
    if (tid == 0) {
        float tt = 0.f;
#pragma unroll
        for (int i = 0; i < 8; i++) tt += red[i];
        rsv = rsqrtf(tt / (float)RANK_ + 1e-6f);
    }
    __syncthreads();
    const float rs = rsv;
    g_kvn[(size_t)m * RANK_ + tid      ] = v0 * rs * knw[tid];
    g_kvn[(size_t)m * RANK_ + tid + 256] = v1 * rs * knw[tid + 256];

    // RoPE k_pe (64 elems = 32 pairs)
    if (tid < 32) {
        float c  = fc[(size_t)s * 64 + 2 * tid];
        float sn = fc[(size_t)s * 64 + 2 * tid + 1];
        float x0 = kvrow[RANK_ + 2 * tid];
        float x1 = kvrow[RANK_ + 2 * tid + 1];
        g_kpe[(size_t)m * 64 + 2 * tid]     = x0 * c - x1 * sn;
        g_kpe[(size_t)m * 64 + 2 * tid + 1] = x0 * sn + x1 * c;
    }

    // RoPE q_pe in place: 16 heads x 32 pairs = 512 pairs
#pragma unroll
    for (int p = tid; p < 512; p += 256) {
        int hh = p >> 5, i = p & 31;
        float c  = fc[(size_t)s * 64 + 2 * i];
        float sn = fc[(size_t)s * 64 + 2 * i + 1];
        size_t idx = (size_t)m * NQ_ + hh * DQK_ + DNOPE_ + 2 * i;
        float x0 = g_q[idx], x1 = g_q[idx + 1];
        g_q[idx]     = x0 * c - x1 * sn;
        g_q[idx + 1] = x0 * sn + x1 * c;
    }
}

// ---------------- flash attention (causal) ----------------
// grid: (S/64 q-tiles, B*NH). 256 threads. Online softmax with 4-thread quads.
#define SSTR 65
#define ATT_SMEM_FLOATS (192*SSTR /*Qs*/ + 192*SSTR /*Ks*/ + 64*SSTR /*Ss*/ + 64*128 /*Vs*/ + 128 /*stats*/)
#define ATT_SMEM_BYTES  (ATT_SMEM_FLOATS * 4)

__global__ void __launch_bounds__(256) k_attn()
{
    extern __shared__ float sm[];
    float* Qs  = sm;                    // [192][65] transposed: Qs[k][row]
    float* Ks  = Qs + 192 * SSTR;       // [192][65] transposed: Ks[k][key]
    float* Ss  = Ks + 192 * SSTR;       // [64][65]  Ss[key][row]
    float* Vs  = Ss + 64 * SSTR;        // [64][128] Vs[key][c]
    float* rsc = Vs + 64 * 128;         // [64] per-row rescale
    float* rl  = rsc + 64;              // [64] per-row final l

    const int tid = threadIdx.x;
    const int bh  = blockIdx.y;
    const int b   = bh >> 4, h = bh & 15;
    const int qt  = gridDim.x - 1 - blockIdx.x;  // heavy tiles first
    const int qb  = qt * 64;
    const float scale = 0.07216878364870322f;    // 1/sqrt(192)

    // load Q tile transposed
    const float* qptr = g_q + (size_t)(b * S_ + qb) * NQ_ + h * DQK_;
    for (int idx = tid; idx < 64 * 192; idx += 256) {
        int r = idx / 192, k = idx - r * 192;
        Qs[k * SSTR + r] = qptr[(size_t)r * NQ_ + k];
    }

    float co[4][8];
#pragma unroll
    for (int i = 0; i < 4; i++)
#pragma unroll
        for (int j = 0; j < 8; j++) co[i][j] = 0.f;

    float m_i = -CUDART_INF_F, l_i = 0.f;
    const int row   = tid >> 2;         // softmax: 4 threads per row
    const int qlane = tid & 3;
    const int qpos  = qb + row;
    const int sk = (tid >> 4) * 4, sr = (tid & 15) * 4;  // score microtile
    const int pr = (tid >> 4) * 4, pc = (tid & 15) * 8;  // PV microtile

    const float* kvu = g_kvup + (size_t)(b * S_) * NUP_ + h * 256;
    const float* kpe = g_kpe  + (size_t)(b * S_) * 64;
    const int ntiles = qt + 1;

    for (int t = 0; t < ntiles; t++) {
        const int kb = t * 64;
        __syncthreads();  // protect Ks/Vs/Ss/rsc from previous iteration

        // load K tile transposed (nope from kv_up, pe broadcast from g_kpe)
        for (int idx = tid; idx < 64 * 192; idx += 256) {
            int n = idx / 192, k = idx - n * 192;
            float v = (k < 128) ? kvu[(size_t)(kb + n) * NUP_ + k]
                                : kpe[(size_t)(kb + n) * 64 + (k - 128)];
            Ks[k * SSTR + n] = v;
        }
        // load V tile
        for (int idx = tid; idx < 64 * 128; idx += 256) {
            int n = idx >> 7, c = idx & 127;
            Vs[idx] = kvu[(size_t)(kb + n) * NUP_ + 128 + c];
        }
        __syncthreads();

        // scores: Ss[key][row] = sum_k Ks[k][key]*Qs[k][row] * scale
        float cs[4][4];
#pragma unroll
        for (int i = 0; i < 4; i++)
#pragma unroll
            for (int j = 0; j < 4; j++) cs[i][j] = 0.f;
        for (int k = 0; k < 192; k++) {
            float rk[4], rq[4];
#pragma unroll
            for (int i = 0; i < 4; i++) rk[i] = Ks[k * SSTR + sk + i];
#pragma unroll
            for (int j = 0; j < 4; j++) rq[j] = Qs[k * SSTR + sr + j];
#pragma unroll
            for (int i = 0; i < 4; i++)
#pragma unroll
                for (int j = 0; j < 4; j++)
                    cs[i][j] = fmaf(rk[i], rq[j], cs[i][j]);
        }
#pragma unroll
        for (int i = 0; i < 4; i++)
#pragma unroll
            for (int j = 0; j < 4; j++)
                Ss[(sk + i) * SSTR + sr + j] = cs[i][j] * scale;
        __syncthreads();

        // online softmax (quad = 4 lanes per row, within one warp)
        float mt = -CUDART_INF_F;
#pragma unroll
        for (int j = 0; j < 16; j++) {
            int k = qlane + j * 4;
            if (kb + k <= qpos) mt = fmaxf(mt, Ss[k * SSTR + row]);
        }
        mt = fmaxf(mt, __shfl_xor_sync(0xffffffffu, mt, 1));
        mt = fmaxf(mt, __shfl_xor_sync(0xffffffffu, mt, 2));
        float nm = fmaxf(m_i, mt);
        float sc = __expf(m_i - nm);  // first tile: exp(-inf)=0
        float ps = 0.f;
#pragma unroll
        for (int j = 0; j < 16; j++) {
            int k = qlane + j * 4;
            float p = 0.f;
            if (kb + k <= qpos) p = __expf(Ss[k * SSTR + row] - nm);
            Ss[k * SSTR + row] = p;
            ps += p;
        }
        ps += __shfl_xor_sync(0xffffffffu, ps, 1);
        ps += __shfl_xor_sync(0xffffffffu, ps, 2);
        l_i = l_i * sc + ps;
        m_i = nm;
        if (qlane == 0) rsc[row] = sc;
        __syncthreads();

        // PV: rescale O then accumulate P*V
        float f[4];
#pragma unroll
        for (int i = 0; i < 4; i++) f[i] = rsc[pr + i];
#pragma unroll
        for (int i = 0; i < 4; i++)
#pragma unroll
            for (int j = 0; j < 8; j++) co[i][j] *= f[i];
        for (int k = 0; k < 64; k++) {
            float p[4];
#pragma unroll
            for (int i = 0; i < 4; i++) p[i] = Ss[k * SSTR + pr + i];
            float4 va = *(const float4*)&Vs[k * 128 + pc];
            float4 vb = *(const float4*)&Vs[k * 128 + pc + 4];
            float vv[8] = {va.x, va.y, va.z, va.w, vb.x, vb.y, vb.z, vb.w};
#pragma unroll
            for (int i = 0; i < 4; i++)
#pragma unroll
                for (int j = 0; j < 8; j++)
                    co[i][j] = fmaf(p[i], vv[j], co[i][j]);
        }
    }

    if (qlane == 0) rl[row] = l_i;
    __syncthreads();

    float* outp = g_attn + (size_t)(b * S_ + qb) * NO_ + h * DV_;
#pragma unroll
    for (int i = 0; i < 4; i++) {
        float inv = 1.f / rl[pr + i];
#pragma unroll
        for (int j = 0; j < 8; j++)
            outp[(size_t)(pr + i) * NO_ + pc + j] = co[i][j] * inv;
    }
}

// ---------------- launch ----------------
extern "C" void kernel_launch(void* const* d_in, const int* in_sizes, int n_in,
                              void* d_out, int out_size)
{
    const float* x   = (const float*)d_in[0];
    // d_in[1] = start_pos (0, unused)
    const float* fc  = (const float*)d_in[2];   // freqs_cis [S,32,2]
    // d_in[3] = mask (causal, implemented directly)
    const float* wq  = (const float*)d_in[4];
    const float* wa  = (const float*)d_in[5];
    const float* wb  = (const float*)d_in[6];
    const float* wo  = (const float*)d_in[7];
    const float* knw = (const float*)d_in[8];
    float* out = (float*)d_out;

    cudaFuncSetAttribute(k_attn, cudaFuncAttributeMaxDynamicSharedMemorySize, ATT_SMEM_BYTES);

    dim3 t(256);
    k_gemm_q   <<<dim3(NQ_/128,  M_/128), t>>>(x, wq);
    k_gemm_kv  <<<dim3((NKV_+127)/128, M_/128), t>>>(x, wa);
    k_ew       <<<M_, 256>>>(fc, knw);
    k_gemm_kvup<<<dim3(NUP_/128, M_/128), t>>>(wb);
    k_attn     <<<dim3(S_/64, B_*NH_), t, ATT_SMEM_BYTES>>>();
    k_gemm_o   <<<dim3(DIM_/128, M_/128), t>>>(wo, out);
}

// round 3
// speedup vs baseline: 1.5942x; 1.5942x over previous
#include <cuda_runtime.h>
#include <cuda_bf16.h>
#include <math_constants.h>
#include <cstdint>

// ---------------- problem constants ----------------
#define B_    2
#define S_    2048
#define DIM_  2048
#define NH_   16
#define DQK_  192
#define DNOPE_ 128
#define DROPE_ 64
#define DV_   128
#define RANK_ 512
#define M_    (B_*S_)          // 4096
#define NQ_   (NH_*DQK_)       // 3072
#define NKV_  (RANK_+DROPE_)   // 576
#define NUP_  (NH_*(DNOPE_+DV_)) // 4096
#define NO_   (NH_*DV_)        // 2048

// ---------------- scratch (device globals; no allocs allowed) ----------------
__device__ __nv_bfloat16 g_xh [M_*DIM_],  g_xl [M_*DIM_];
__device__ __nv_bfloat16 g_wqh[NQ_*DIM_], g_wql[NQ_*DIM_];
__device__ __nv_bfloat16 g_wah[NKV_*DIM_],g_wal[NKV_*DIM_];
__device__ __nv_bfloat16 g_wbh[NUP_*RANK_],g_wbl[NUP_*RANK_];
__device__ __nv_bfloat16 g_woh[DIM_*NO_], g_wol[DIM_*NO_];
__device__ __nv_bfloat16 g_kvnh[M_*RANK_],g_kvnl[M_*RANK_];
__device__ __nv_bfloat16 g_ath[M_*NO_],   g_atl[M_*NO_];
__device__ float g_q   [M_*NQ_];
__device__ float g_kv  [M_*NKV_];
__device__ float g_kpe [M_*DROPE_];
__device__ float g_kvup[M_*NUP_];

// ---------------- PTX helpers (all base sm_80-era, legal on sm_103 target) ----
__device__ __forceinline__ uint32_t smem_u32(const void* p){
    uint32_t a;
    asm("{ .reg .u64 t; cvta.to.shared.u64 t, %1; cvt.u32.u64 %0, t; }"
        : "=r"(a) : "l"(p));
    return a;
}
__device__ __forceinline__ void cpa16(uint32_t dst, const void* src, int sz){
    asm volatile("cp.async.cg.shared.global [%0], [%1], 16, %2;"
                 :: "r"(dst), "l"(src), "r"(sz) : "memory");
}
#define CP_COMMIT() asm volatile("cp.async.commit_group;" ::: "memory")
#define CP_WAIT2()  asm volatile("cp.async.wait_group 2;" ::: "memory")

__device__ __forceinline__ void ldsm4(uint32_t* r, uint32_t addr){
    asm volatile("ldmatrix.sync.aligned.m8n8.x4.shared.b16 {%0,%1,%2,%3}, [%4];"
        : "=r"(r[0]), "=r"(r[1]), "=r"(r[2]), "=r"(r[3]) : "r"(addr));
}
__device__ __forceinline__ void mma16816(float* c, const uint32_t* a,
                                         uint32_t b0, uint32_t b1){
    asm volatile("mma.sync.aligned.m16n8k16.row.col.f32.bf16.bf16.f32 "
        "{%0,%1,%2,%3}, {%4,%5,%6,%7}, {%8,%9}, {%0,%1,%2,%3};"
        : "+f"(c[0]), "+f"(c[1]), "+f"(c[2]), "+f"(c[3])
        : "r"(a[0]), "r"(a[1]), "r"(a[2]), "r"(a[3]), "r"(b0), "r"(b1));
}

// ---------------- hi/lo bf16 split ----------------
__device__ __forceinline__ void split_bf16(float v, __nv_bfloat16& h, __nv_bfloat16& l){
    h = __float2bfloat16(v);
    l = __float2bfloat16(v - __bfloat162float(h));
}

__global__ void __launch_bounds__(256) k_cvt(const float* __restrict__ s,
                                             __nv_bfloat16* __restrict__ h,
                                             __nv_bfloat16* __restrict__ l, int n)
{
    int i = (blockIdx.x * 256 + threadIdx.x) * 4;
    if (i >= n) return;
    float4 v = *(const float4*)(s + i);
    __nv_bfloat16 h0, l0, h1, l1, h2, l2, h3, l3;
    split_bf16(v.x, h0, l0); split_bf16(v.y, h1, l1);
    split_bf16(v.z, h2, l2); split_bf16(v.w, h3, l3);
    __nv_bfloat162 p;
    p.x = h0; p.y = h1; *(__nv_bfloat162*)(h + i)     = p;
    p.x = h2; p.y = h3; *(__nv_bfloat162*)(h + i + 2) = p;
    p.x = l0; p.y = l1; *(__nv_bfloat162*)(l + i)     = p;
    p.x = l2; p.y = l3; *(__nv_bfloat162*)(l + i + 2) = p;
}

// ---------------- mma.sync GEMM: C[M,N] = A[M,K] * W[N,K]^T ------------------
// 128x128 tile, BK=32, 3-stage cp.async pipeline, 3-term bf16 emulation.
// smem stage layout: [Ah 8K][Al 8K][Bh 8K][Bl 8K]; row = 64B (32 bf16),
// 16B chunks XOR-swizzled by (row&3).
#define STG_BYTES 32768
#define GEMM_SMEM (3*STG_BYTES)   // 98304

__device__ __forceinline__ void stage_load(uint32_t sdst,
    const char* ah, const char* al, const char* bh, const char* bl,
    int K2, int k0b, int nrem)
{
    const int tid = threadIdx.x;
#pragma unroll
    for (int p = 0; p < 2; p++){
        int idx = tid + p*256;
        int r = idx >> 2, c = idx & 3;
        uint32_t soff = (uint32_t)(r*64 + ((c ^ (r & 3)) << 4));
        size_t go = (size_t)r * K2 + k0b + c*16;
        cpa16(sdst + soff,        ah + go, 16);
        cpa16(sdst + 8192 + soff, al + go, 16);
        int rb = (r < nrem) ? r : 0;
        int sz = (r < nrem) ? 16 : 0;
        size_t gob = (size_t)rb * K2 + k0b + c*16;
        cpa16(sdst + 16384 + soff, bh + gob, sz);
        cpa16(sdst + 24576 + soff, bl + gob, sz);
    }
}

__global__ void __launch_bounds__(256, 2)
k_mmagemm(const __nv_bfloat16* __restrict__ Ah, const __nv_bfloat16* __restrict__ Al,
          const __nv_bfloat16* __restrict__ Bh, const __nv_bfloat16* __restrict__ Bl,
          float* __restrict__ C, int M, int N, int K)
{
    extern __shared__ char smc[];
    const int tid = threadIdx.x, wid = tid >> 5, lane = tid & 31;
    const int m0 = blockIdx.y * 128, n0 = blockIdx.x * 128;
    const int wm = (wid & 3) * 32, wn = (wid >> 2) * 64;
    const int nrem = N - n0;
    const int K2 = K * 2;
    const int nk = K / 32;

    uint32_t sbase = smem_u32(smc);
    const char* gAh = (const char*)(Ah + (size_t)m0 * K);
    const char* gAl = (const char*)(Al + (size_t)m0 * K);
    const char* gBh = (const char*)(Bh + (size_t)n0 * K);
    const char* gBl = (const char*)(Bl + (size_t)n0 * K);

    // prologue: stages 0,1
#pragma unroll
    for (int s = 0; s < 2; s++){
        stage_load(sbase + s*STG_BYTES, gAh, gAl, gBh, gBl, K2, s*64, nrem);
        CP_COMMIT();
    }

    float acc[2][8][4];
#pragma unroll
    for (int a = 0; a < 2; a++)
#pragma unroll
        for (int b = 0; b < 8; b++)
#pragma unroll
            for (int c = 0; c < 4; c++) acc[a][b][c] = 0.f;

    int sidx = 0;  // stage index of compute buffer
    for (int kt = 0; kt < nk; kt++){
        int ns = kt + 2;
        if (ns < nk){
            int fs = ns - 3*(ns/3);
            stage_load(sbase + fs*STG_BYTES, gAh, gAl, gBh, gBl, K2, ns*64, nrem);
        }
        CP_COMMIT();
        CP_WAIT2();
        __syncthreads();

        uint32_t sb = sbase + sidx*STG_BYTES;
#pragma unroll
        for (int ks = 0; ks < 2; ks++){
            uint32_t afr[2][2][4];
#pragma unroll
            for (int v = 0; v < 2; v++)
#pragma unroll
                for (int mt = 0; mt < 2; mt++){
                    int row = wm + mt*16 + (lane & 15);
                    int ch  = ((ks*2 + (lane >> 4)) ^ (row & 3)) & 3;
                    ldsm4(afr[v][mt], sb + v*8192 + row*64 + ch*16);
                }
#pragma unroll
            for (int np = 0; np < 4; np++){
                uint32_t bh4[4], bl4[4];
                int row = wn + np*16 + ((lane >> 4) << 3) + (lane & 7);
                int ch  = ((ks*2 + ((lane >> 3) & 1)) ^ (row & 3)) & 3;
                ldsm4(bh4, sb + 16384 + row*64 + ch*16);
                ldsm4(bl4, sb + 24576 + row*64 + ch*16);
#pragma unroll
                for (int mt = 0; mt < 2; mt++)
#pragma unroll
                    for (int h = 0; h < 2; h++){
                        float* c = acc[mt][np*2 + h];
                        mma16816(c, afr[0][mt], bh4[2*h], bh4[2*h+1]);
                        mma16816(c, afr[0][mt], bl4[2*h], bl4[2*h+1]);
                        mma16816(c, afr[1][mt], bh4[2*h], bh4[2*h+1]);
                    }
            }
        }
        __syncthreads();
        sidx = (sidx + 1 == 3) ? 0 : sidx + 1;
    }

    // epilogue
#pragma unroll
    for (int mt = 0; mt < 2; mt++){
        int row = m0 + wm + mt*16 + (lane >> 2);
#pragma unroll
        for (int nt = 0; nt < 8; nt++){
            int col = n0 + wn + nt*8 + (lane & 3)*2;
            if (col < N){
                float* c = acc[mt][nt];
                *(float2*)(C + (size_t)row*N + col)     = make_float2(c[0], c[1]);
                *(float2*)(C + (size_t)(row+8)*N + col) = make_float2(c[2], c[3]);
            }
        }
    }
}

// ---------------- fused elementwise: rmsnorm + both RoPEs ----------------
__global__ void __launch_bounds__(256) k_ew(const float* __restrict__ fc,
                                            const float* __restrict__ knw)
{
    __shared__ float red[8];
    __shared__ float rsv;
    const int m   = blockIdx.x;
    const int s   = m & (S_ - 1);
    const int tid = threadIdx.x;
    const float* kvrow = g_kv + (size_t)m * NKV_;

    float v0 = kvrow[tid];
    float v1 = kvrow[tid + 256];
    float ss = v0 * v0 + v1 * v1;
#pragma unroll
    for (int o = 16; o; o >>= 1) ss += __shfl_xor_sync(0xffffffffu, ss, o);
    if ((tid & 31) == 0) red[tid >> 5] = ss;
    __syncthreads();
    if (tid == 0) {
        float tt = 0.f;
#pragma unroll
        for (int i = 0; i < 8; i++) tt += red[i];
        rsv = rsqrtf(tt / (float)RANK_ + 1e-6f);
    }
    __syncthreads();
    const float rs = rsv;
    {
        float y0 = v0 * rs * knw[tid];
        float y1 = v1 * rs * knw[tid + 256];
        size_t o0 = (size_t)m * RANK_ + tid;
        __nv_bfloat16 h, l;
        split_bf16(y0, h, l); g_kvnh[o0]       = h; g_kvnl[o0]       = l;
        split_bf16(y1, h, l); g_kvnh[o0 + 256] = h; g_kvnl[o0 + 256] = l;
    }

    if (tid < 32) {
        float c  = fc[(size_t)s * 64 + 2 * tid];
        float sn = fc[(size_t)s * 64 + 2 * tid + 1];
        float x0 = kvrow[RANK_ + 2 * tid];
        float x1 = kvrow[RANK_ + 2 * tid + 1];
        g_kpe[(size_t)m * 64 + 2 * tid]     = x0 * c - x1 * sn;
        g_kpe[(size_t)m * 64 + 2 * tid + 1] = x0 * sn + x1 * c;
    }

#pragma unroll
    for (int p = tid; p < 512; p += 256) {
        int hh = p >> 5, i = p & 31;
        float c  = fc[(size_t)s * 64 + 2 * i];
        float sn = fc[(size_t)s * 64 + 2 * i + 1];
        size_t idx = (size_t)m * NQ_ + hh * DQK_ + DNOPE_ + 2 * i;
        float x0 = g_q[idx], x1 = g_q[idx + 1];
        g_q[idx]     = x0 * c - x1 * sn;
        g_q[idx + 1] = x0 * sn + x1 * c;
    }
}

// ---------------- flash attention (causal, fp32 FFMA) ----------------
#define SSTR 65
#define ATT_SMEM_FLOATS (192*SSTR + 192*SSTR + 64*SSTR + 64*128 + 128)
#define ATT_SMEM_BYTES  (ATT_SMEM_FLOATS * 4)

__global__ void __launch_bounds__(256) k_attn()
{
    extern __shared__ float sm[];
    float* Qs  = sm;
    float* Ks  = Qs + 192 * SSTR;
    float* Ss  = Ks + 192 * SSTR;
    float* Vs  = Ss + 64 * SSTR;
    float* rsc = Vs + 64 * 128;
    float* rl  = rsc + 64;

    const int tid = threadIdx.x;
    const int bh  = blockIdx.y;
    const int b   = bh >> 4, h = bh & 15;
    const int qt  = gridDim.x - 1 - blockIdx.x;
    const int qb  = qt * 64;
    const float scale = 0.07216878364870322f;  // 1/sqrt(192)

    const float* qptr = g_q + (size_t)(b * S_ + qb) * NQ_ + h * DQK_;
    for (int idx = tid; idx < 64 * 192; idx += 256) {
        int r = idx / 192, k = idx - r * 192;
        Qs[k * SSTR + r] = qptr[(size_t)r * NQ_ + k];
    }

    float co[4][8];
#pragma unroll
    for (int i = 0; i < 4; i++)
#pragma unroll
        for (int j = 0; j < 8; j++) co[i][j] = 0.f;

    float m_i = -CUDART_INF_F, l_i = 0.f;
    const int row   = tid >> 2;
    const int qlane = tid & 3;
    const int qpos  = qb + row;
    const int sk = (tid >> 4) * 4, sr = (tid & 15) * 4;
    const int pr = (tid >> 4) * 4, pc = (tid & 15) * 8;

    const float* kvu = g_kvup + (size_t)(b * S_) * NUP_ + h * 256;
    const float* kpe = g_kpe  + (size_t)(b * S_) * 64;
    const int ntiles = qt + 1;

    for (int t = 0; t < ntiles; t++) {
        const int kb = t * 64;
        __syncthreads();

        for (int idx = tid; idx < 64 * 192; idx += 256) {
            int n = idx / 192, k = idx - n * 192;
            float v = (k < 128) ? kvu[(size_t)(kb + n) * NUP_ + k]
                                : kpe[(size_t)(kb + n) * 64 + (k - 128)];
            Ks[k * SSTR + n] = v;
        }
        for (int idx = tid; idx < 64 * 128; idx += 256) {
            int n = idx >> 7, c = idx & 127;
            Vs[idx] = kvu[(size_t)(kb + n) * NUP_ + 128 + c];
        }
        __syncthreads();

        float cs[4][4];
#pragma unroll
        for (int i = 0; i < 4; i++)
#pragma unroll
            for (int j = 0; j < 4; j++) cs[i][j] = 0.f;
        for (int k = 0; k < 192; k++) {
            float rk[4], rq[4];
#pragma unroll
            for (int i = 0; i < 4; i++) rk[i] = Ks[k * SSTR + sk + i];
#pragma unroll
            for (int j = 0; j < 4; j++) rq[j] = Qs[k * SSTR + sr + j];
#pragma unroll
            for (int i = 0; i < 4; i++)
#pragma unroll
                for (int j = 0; j < 4; j++)
                    cs[i][j] = fmaf(rk[i], rq[j], cs[i][j]);
        }
#pragma unroll
        for (int i = 0; i < 4; i++)
#pragma unroll
            for (int j = 0; j < 4; j++)
                Ss[(sk + i) * SSTR + sr + j] = cs[i][j] * scale;
        __syncthreads();

        float mt = -CUDART_INF_F;
#pragma unroll
        for (int j = 0; j < 16; j++) {
            int k = qlane + j * 4;
            if (kb + k <= qpos) mt = fmaxf(mt, Ss[k * SSTR + row]);
        }
        mt = fmaxf(mt, __shfl_xor_sync(0xffffffffu, mt, 1));
        mt = fmaxf(mt, __shfl_xor_sync(0xffffffffu, mt, 2));
        float nm = fmaxf(m_i, mt);
        float sc = __expf(m_i - nm);
        float ps = 0.f;
#pragma unroll
        for (int j = 0; j < 16; j++) {
            int k = qlane + j * 4;
            float p = 0.f;
            if (kb + k <= qpos) p = __expf(Ss[k * SSTR + row] - nm);
            Ss[k * SSTR + row] = p;
            ps += p;
        }
        ps += __shfl_xor_sync(0xffffffffu, ps, 1);
        ps += __shfl_xor_sync(0xffffffffu, ps, 2);
        l_i = l_i * sc + ps;
        m_i = nm;
        if (qlane == 0) rsc[row] = sc;
        __syncthreads();

        float f[4];
#pragma unroll
        for (int i = 0; i < 4; i++) f[i] = rsc[pr + i];
#pragma unroll
        for (int i = 0; i < 4; i++)
#pragma unroll
            for (int j = 0; j < 8; j++) co[i][j] *= f[i];
        for (int k = 0; k < 64; k++) {
            float p[4];
#pragma unroll
            for (int i = 0; i < 4; i++) p[i] = Ss[k * SSTR + pr + i];
            float4 va = *(const float4*)&Vs[k * 128 + pc];
            float4 vb = *(const float4*)&Vs[k * 128 + pc + 4];
            float vv[8] = {va.x, va.y, va.z, va.w, vb.x, vb.y, vb.z, vb.w};
#pragma unroll
            for (int i = 0; i < 4; i++)
#pragma unroll
                for (int j = 0; j < 8; j++)
                    co[i][j] = fmaf(p[i], vv[j], co[i][j]);
        }
    }

    if (qlane == 0) rl[row] = l_i;
    __syncthreads();

    __nv_bfloat16* oh = g_ath + (size_t)(b * S_ + qb) * NO_ + h * DV_;
    __nv_bfloat16* ol = g_atl + (size_t)(b * S_ + qb) * NO_ + h * DV_;
#pragma unroll
    for (int i = 0; i < 4; i++) {
        float inv = 1.f / rl[pr + i];
#pragma unroll
        for (int j = 0; j < 8; j++) {
            float v = co[i][j] * inv;
            __nv_bfloat16 hh, ll;
            split_bf16(v, hh, ll);
            size_t o = (size_t)(pr + i) * NO_ + pc + j;
            oh[o] = hh; ol[o] = ll;
        }
    }
}

// ---------------- launch ----------------
static void* sym_addr(const void* s) { void* p = nullptr; cudaGetSymbolAddress(&p, s); return p; }

extern "C" void kernel_launch(void* const* d_in, const int* in_sizes, int n_in,
                              void* d_out, int out_size)
{
    const float* x   = (const float*)d_in[0];
    const float* fc  = (const float*)d_in[2];
    const float* wq  = (const float*)d_in[4];
    const float* wa  = (const float*)d_in[5];
    const float* wb  = (const float*)d_in[6];
    const float* wo  = (const float*)d_in[7];
    const float* knw = (const float*)d_in[8];
    float* out = (float*)d_out;

    cudaFuncSetAttribute(k_attn,    cudaFuncAttributeMaxDynamicSharedMemorySize, ATT_SMEM_BYTES);
    cudaFuncSetAttribute(k_mmagemm, cudaFuncAttributeMaxDynamicSharedMemorySize, GEMM_SMEM);

    __nv_bfloat16 *xh  = (__nv_bfloat16*)sym_addr(g_xh),  *xl  = (__nv_bfloat16*)sym_addr(g_xl);
    __nv_bfloat16 *wqh = (__nv_bfloat16*)sym_addr(g_wqh), *wql = (__nv_bfloat16*)sym_addr(g_wql);
    __nv_bfloat16 *wah = (__nv_bfloat16*)sym_addr(g_wah), *wal = (__nv_bfloat16*)sym_addr(g_wal);
    __nv_bfloat16 *wbh = (__nv_bfloat16*)sym_addr(g_wbh), *wbl = (__nv_bfloat16*)sym_addr(g_wbl);
    __nv_bfloat16 *woh = (__nv_bfloat16*)sym_addr(g_woh), *wol = (__nv_bfloat16*)sym_addr(g_wol);
    __nv_bfloat16 *kvh = (__nv_bfloat16*)sym_addr(g_kvnh),*kvl = (__nv_bfloat16*)sym_addr(g_kvnl);
    __nv_bfloat16 *ath = (__nv_bfloat16*)sym_addr(g_ath), *atl = (__nv_bfloat16*)sym_addr(g_atl);
    float *qf  = (float*)sym_addr(g_q);
    float *kvf = (float*)sym_addr(g_kv);

    dim3 t(256);
    k_cvt<<<(M_*DIM_)/1024,   t>>>(x,  xh,  xl,  M_*DIM_);
    k_cvt<<<(NQ_*DIM_)/1024,  t>>>(wq, wqh, wql, NQ_*DIM_);
    k_cvt<<<(NKV_*DIM_)/1024, t>>>(wa, wah, wal, NKV_*DIM_);
    k_cvt<<<(NUP_*RANK_)/1024,t>>>(wb, wbh, wbl, NUP_*RANK_);
    k_cvt<<<(DIM_*NO_)/1024,  t>>>(wo, woh, wol, DIM_*NO_);

    // q = x @ wq^T   [4096 x 3072], K=2048
    k_mmagemm<<<dim3(NQ_/128, M_/128), t, GEMM_SMEM>>>(xh, xl, wqh, wql, qf, M_, NQ_, DIM_);
    // kv = x @ wkv_a^T  [4096 x 576], K=2048
    k_mmagemm<<<dim3((NKV_+127)/128, M_/128), t, GEMM_SMEM>>>(xh, xl, wah, wal, kvf, M_, NKV_, DIM_);
    // rmsnorm + ropes
    k_ew<<<M_, 256>>>(fc, knw);
    // kv_up = kvn @ wkv_b^T  [4096 x 4096], K=512
    k_mmagemm<<<dim3(NUP_/128, M_/128), t, GEMM_SMEM>>>(kvh, kvl, wbh, wbl,
                                                        (float*)sym_addr(g_kvup), M_, NUP_, RANK_);
    // attention
    k_attn<<<dim3(S_/64, B_*NH_), t, ATT_SMEM_BYTES>>>();
    // out = attn @ wo^T  [4096 x 2048], K=2048
    k_mmagemm<<<dim3(DIM_/128, M_/128), t, GEMM_SMEM>>>(ath, atl, woh, wol, out, M_, DIM_, NO_);
}

// round 4
// speedup vs baseline: 4.3137x; 2.7058x over previous
#include <cuda_runtime.h>
#include <cuda_bf16.h>
#include <math_constants.h>
#include <cstdint>

// ---------------- problem constants ----------------
#define B_    2
#define S_    2048
#define DIM_  2048
#define NH_   16
#define DQK_  192
#define DNOPE_ 128
#define DROPE_ 64
#define DV_   128
#define RANK_ 512
#define M_    (B_*S_)          // 4096
#define NQ_   (NH_*DQK_)       // 3072
#define NKV_  (RANK_+DROPE_)   // 576
#define NUP_  (NH_*(DNOPE_+DV_)) // 4096
#define NO_   (NH_*DV_)        // 2048

// ---------------- scratch (device globals; no allocs allowed) ----------------
__device__ __nv_bfloat16 g_xh [M_*DIM_],  g_xl [M_*DIM_];
__device__ __nv_bfloat16 g_wqh[NQ_*DIM_], g_wql[NQ_*DIM_];
__device__ __nv_bfloat16 g_wah[NKV_*DIM_],g_wal[NKV_*DIM_];
__device__ __nv_bfloat16 g_wbh[NUP_*RANK_],g_wbl[NUP_*RANK_];
__device__ __nv_bfloat16 g_woh[DIM_*NO_], g_wol[DIM_*NO_];
__device__ __nv_bfloat16 g_kvnh[M_*RANK_],g_kvnl[M_*RANK_];
__device__ __nv_bfloat16 g_ath[M_*NO_],   g_atl[M_*NO_];
__device__ float g_q   [M_*NQ_];
__device__ float g_kv  [M_*NKV_];
__device__ float g_kpe [M_*DROPE_];
__device__ float g_kvup[M_*NUP_];
// head-major bf16 hi/lo operands for attention
__device__ __nv_bfloat16 g_qh[B_*NH_*S_*DQK_], g_ql[B_*NH_*S_*DQK_];
__device__ __nv_bfloat16 g_kh[B_*NH_*S_*DQK_], g_kl[B_*NH_*S_*DQK_];
__device__ __nv_bfloat16 g_vh[B_*NH_*S_*DV_],  g_vl[B_*NH_*S_*DV_];

// ---------------- PTX helpers ----------------
__device__ __forceinline__ uint32_t smem_u32(const void* p){
    uint32_t a;
    asm("{ .reg .u64 t; cvta.to.shared.u64 t, %1; cvt.u32.u64 %0, t; }"
        : "=r"(a) : "l"(p));
    return a;
}
__device__ __forceinline__ void cpa16(uint32_t dst, const void* src, int sz){
    asm volatile("cp.async.cg.shared.global [%0], [%1], 16, %2;"
                 :: "r"(dst), "l"(src), "r"(sz) : "memory");
}
#define CP_COMMIT() asm volatile("cp.async.commit_group;" ::: "memory")
#define CP_WAIT2()  asm volatile("cp.async.wait_group 2;" ::: "memory")
#define CP_WAIT1()  asm volatile("cp.async.wait_group 1;" ::: "memory")
#define CP_WAIT0()  asm volatile("cp.async.wait_group 0;" ::: "memory")

__device__ __forceinline__ void ldsm4(uint32_t* r, uint32_t addr){
    asm volatile("ldmatrix.sync.aligned.m8n8.x4.shared.b16 {%0,%1,%2,%3}, [%4];"
        : "=r"(r[0]), "=r"(r[1]), "=r"(r[2]), "=r"(r[3]) : "r"(addr));
}
__device__ __forceinline__ void ldsm4t(uint32_t* r, uint32_t addr){
    asm volatile("ldmatrix.sync.aligned.m8n8.x4.trans.shared.b16 {%0,%1,%2,%3}, [%4];"
        : "=r"(r[0]), "=r"(r[1]), "=r"(r[2]), "=r"(r[3]) : "r"(addr));
}
__device__ __forceinline__ void mma16816(float* c, const uint32_t* a,
                                         uint32_t b0, uint32_t b1){
    asm volatile("mma.sync.aligned.m16n8k16.row.col.f32.bf16.bf16.f32 "
        "{%0,%1,%2,%3}, {%4,%5,%6,%7}, {%8,%9}, {%0,%1,%2,%3};"
        : "+f"(c[0]), "+f"(c[1]), "+f"(c[2]), "+f"(c[3])
        : "r"(a[0]), "r"(a[1]), "r"(a[2]), "r"(a[3]), "r"(b0), "r"(b1));
}
__device__ __forceinline__ float ex2f(float x){
    float y; asm("ex2.approx.ftz.f32 %0, %1;" : "=f"(y) : "f"(x)); return y;
}

// ---------------- hi/lo bf16 split ----------------
__device__ __forceinline__ void split_bf16(float v, __nv_bfloat16& h, __nv_bfloat16& l){
    h = __float2bfloat16(v);
    l = __float2bfloat16(v - __bfloat162float(h));
}
__device__ __forceinline__ void pksplit(float a, float b, uint32_t& hi, uint32_t& lo){
    __nv_bfloat16 ah, al, bh, bl;
    split_bf16(a, ah, al); split_bf16(b, bh, bl);
    __nv_bfloat162 H; H.x = ah; H.y = bh; hi = *(uint32_t*)&H;
    __nv_bfloat162 L; L.x = al; L.y = bl; lo = *(uint32_t*)&L;
}

__global__ void __launch_bounds__(256) k_cvt(const float* __restrict__ s,
                                             __nv_bfloat16* __restrict__ h,
                                             __nv_bfloat16* __restrict__ l, int n)
{
    int i = (blockIdx.x * 256 + threadIdx.x) * 4;
    if (i >= n) return;
    float4 v = *(const float4*)(s + i);
    __nv_bfloat16 h0, l0, h1, l1, h2, l2, h3, l3;
    split_bf16(v.x, h0, l0); split_bf16(v.y, h1, l1);
    split_bf16(v.z, h2, l2); split_bf16(v.w, h3, l3);
    __nv_bfloat162 p;
    p.x = h0; p.y = h1; *(__nv_bfloat162*)(h + i)     = p;
    p.x = h2; p.y = h3; *(__nv_bfloat162*)(h + i + 2) = p;
    p.x = l0; p.y = l1; *(__nv_bfloat162*)(l + i)     = p;
    p.x = l2; p.y = l3; *(__nv_bfloat162*)(l + i + 2) = p;
}

// ---------------- mma.sync GEMM (unchanged from R3) ------------------
#define STG_BYTES 32768
#define GEMM_SMEM (3*STG_BYTES)

__device__ __forceinline__ void stage_load(uint32_t sdst,
    const char* ah, const char* al, const char* bh, const char* bl,
    int K2, int k0b, int nrem)
{
    const int tid = threadIdx.x;
#pragma unroll
    for (int p = 0; p < 2; p++){
        int idx = tid + p*256;
        int r = idx >> 2, c = idx & 3;
        uint32_t soff = (uint32_t)(r*64 + ((c ^ (r & 3)) << 4));
        size_t go = (size_t)r * K2 + k0b + c*16;
        cpa16(sdst + soff,        ah + go, 16);
        cpa16(sdst + 8192 + soff, al + go, 16);
        int rb = (r < nrem) ? r : 0;
        int sz = (r < nrem) ? 16 : 0;
        size_t gob = (size_t)rb * K2 + k0b + c*16;
        cpa16(sdst + 16384 + soff, bh + gob, sz);
        cpa16(sdst + 24576 + soff, bl + gob, sz);
    }
}

__global__ void __launch_bounds__(256, 2)
k_mmagemm(const __nv_bfloat16* __restrict__ Ah, const __nv_bfloat16* __restrict__ Al,
          const __nv_bfloat16* __restrict__ Bh, const __nv_bfloat16* __restrict__ Bl,
          float* __restrict__ C, int M, int N, int K)
{
    extern __shared__ char smc[];
    const int tid = threadIdx.x, wid = tid >> 5, lane = tid & 31;
    const int m0 = blockIdx.y * 128, n0 = blockIdx.x * 128;
    const int wm = (wid & 3) * 32, wn = (wid >> 2) * 64;
    const int nrem = N - n0;
    const int K2 = K * 2;
    const int nk = K / 32;

    uint32_t sbase = smem_u32(smc);
    const char* gAh = (const char*)(Ah + (size_t)m0 * K);
    const char* gAl = (const char*)(Al + (size_t)m0 * K);
    const char* gBh = (const char*)(Bh + (size_t)n0 * K);
    const char* gBl = (const char*)(Bl + (size_t)n0 * K);

#pragma unroll
    for (int s = 0; s < 2; s++){
        stage_load(sbase + s*STG_BYTES, gAh, gAl, gBh, gBl, K2, s*64, nrem);
        CP_COMMIT();
    }

    float acc[2][8][4];
#pragma unroll
    for (int a = 0; a < 2; a++)
#pragma unroll
        for (int b = 0; b < 8; b++)
#pragma unroll
            for (int c = 0; c < 4; c++) acc[a][b][c] = 0.f;

    int sidx = 0;
    for (int kt = 0; kt < nk; kt++){
        int ns = kt + 2;
        if (ns < nk){
            int fs = ns - 3*(ns/3);
            stage_load(sbase + fs*STG_BYTES, gAh, gAl, gBh, gBl, K2, ns*64, nrem);
        }
        CP_COMMIT();
        CP_WAIT2();
        __syncthreads();

        uint32_t sb = sbase + sidx*STG_BYTES;
#pragma unroll
        for (int ks = 0; ks < 2; ks++){
            uint32_t afr[2][2][4];
#pragma unroll
            for (int v = 0; v < 2; v++)
#pragma unroll
                for (int mt = 0; mt < 2; mt++){
                    int row = wm + mt*16 + (lane & 15);
                    int ch  = ((ks*2 + (lane >> 4)) ^ (row & 3)) & 3;
                    ldsm4(afr[v][mt], sb + v*8192 + row*64 + ch*16);
                }
#pragma unroll
            for (int np = 0; np < 4; np++){
                uint32_t bh4[4], bl4[4];
                int row = wn + np*16 + ((lane >> 4) << 3) + (lane & 7);
                int ch  = ((ks*2 + ((lane >> 3) & 1)) ^ (row & 3)) & 3;
                ldsm4(bh4, sb + 16384 + row*64 + ch*16);
                ldsm4(bl4, sb + 24576 + row*64 + ch*16);
#pragma unroll
                for (int mt = 0; mt < 2; mt++)
#pragma unroll
                    for (int h = 0; h < 2; h++){
                        float* c = acc[mt][np*2 + h];
                        mma16816(c, afr[0][mt], bh4[2*h], bh4[2*h+1]);
                        mma16816(c, afr[0][mt], bl4[2*h], bl4[2*h+1]);
                        mma16816(c, afr[1][mt], bh4[2*h], bh4[2*h+1]);
                    }
            }
        }
        __syncthreads();
        sidx = (sidx + 1 == 3) ? 0 : sidx + 1;
    }

#pragma unroll
    for (int mt = 0; mt < 2; mt++){
        int row = m0 + wm + mt*16 + (lane >> 2);
#pragma unroll
        for (int nt = 0; nt < 8; nt++){
            int col = n0 + wn + nt*8 + (lane & 3)*2;
            if (col < N){
                float* c = acc[mt][nt];
                *(float2*)(C + (size_t)row*N + col)     = make_float2(c[0], c[1]);
                *(float2*)(C + (size_t)(row+8)*N + col) = make_float2(c[2], c[3]);
            }
        }
    }
}

// ---------------- fused elementwise: rmsnorm + both RoPEs ----------------
__global__ void __launch_bounds__(256) k_ew(const float* __restrict__ fc,
                                            const float* __restrict__ knw)
{
    __shared__ float red[8];
    __shared__ float rsv;
    const int m   = blockIdx.x;
    const int s   = m & (S_ - 1);
    const int tid = threadIdx.x;
    const float* kvrow = g_kv + (size_t)m * NKV_;

    float v0 = kvrow[tid];
    float v1 = kvrow[tid + 256];
    float ss = v0 * v0 + v1 * v1;
#pragma unroll
    for (int o = 16; o; o >>= 1) ss += __shfl_xor_sync(0xffffffffu, ss, o);
    if ((tid & 31) == 0) red[tid >> 5] = ss;
    __syncthreads();
    if (tid == 0) {
        float tt = 0.f;
#pragma unroll
        for (int i = 0; i < 8; i++) tt += red[i];
        rsv = rsqrtf(tt / (float)RANK_ + 1e-6f);
    }
    __syncthreads();
    const float rs = rsv;
    {
        float y0 = v0 * rs * knw[tid];
        float y1 = v1 * rs * knw[tid + 256];
        size_t o0 = (size_t)m * RANK_ + tid;
        __nv_bfloat16 h, l;
        split_bf16(y0, h, l); g_kvnh[o0]       = h; g_kvnl[o0]       = l;
        split_bf16(y1, h, l); g_kvnh[o0 + 256] = h; g_kvnl[o0 + 256] = l;
    }

    if (tid < 32) {
        float c  = fc[(size_t)s * 64 + 2 * tid];
        float sn = fc[(size_t)s * 64 + 2 * tid + 1];
        float x0 = kvrow[RANK_ + 2 * tid];
        float x1 = kvrow[RANK_ + 2 * tid + 1];
        g_kpe[(size_t)m * 64 + 2 * tid]     = x0 * c - x1 * sn;
        g_kpe[(size_t)m * 64 + 2 * tid + 1] = x0 * sn + x1 * c;
    }

#pragma unroll
    for (int p = tid; p < 512; p += 256) {
        int hh = p >> 5, i = p & 31;
        float c  = fc[(size_t)s * 64 + 2 * i];
        float sn = fc[(size_t)s * 64 + 2 * i + 1];
        size_t idx = (size_t)m * NQ_ + hh * DQK_ + DNOPE_ + 2 * i;
        float x0 = g_q[idx], x1 = g_q[idx + 1];
        g_q[idx]     = x0 * c - x1 * sn;
        g_q[idx + 1] = x0 * sn + x1 * c;
    }
}

// ---------------- Q/K/V conversion to head-major bf16 hi/lo -----------------
__global__ void __launch_bounds__(256) k_qkvcvt()
{
    const int m = blockIdx.x;             // b*2048 + s
    const int b = m >> 11, s = m & 2047;
    const int tid = threadIdx.x;
    __nv_bfloat16 H, L;

    for (int i = tid; i < 16*192; i += 256){
        int hh = i / 192, d = i - hh*192;
        size_t o = ((size_t)(b*16 + hh) * S_ + s) * 192 + d;
        float qv = g_q[(size_t)m * NQ_ + hh*192 + d];
        split_bf16(qv, H, L); g_qh[o] = H; g_ql[o] = L;
        float kvv = (d < 128) ? g_kvup[(size_t)m * NUP_ + hh*256 + d]
                              : g_kpe[(size_t)m * 64 + d - 128];
        split_bf16(kvv, H, L); g_kh[o] = H; g_kl[o] = L;
    }
    for (int i = tid; i < 16*128; i += 256){
        int hh = i >> 7, d = i & 127;
        float vv = g_kvup[(size_t)m * NUP_ + hh*256 + 128 + d];
        split_bf16(vv, H, L);
        size_t o = ((size_t)(b*16 + hh) * S_ + s) * 128 + d;
        g_vh[o] = H; g_vl[o] = L;
    }
}

// ---------------- HMMA flash attention (causal) ----------------
// 256 thr / 8 warps; q-tile 128 (16 rows/warp), key-tile 64; Q in registers;
// K/V double-buffered cp.async. 3-term bf16 emulation for QK^T and PV.
// stage layout: Kh[0,24576) Kl[24576,49152) Vh[49152,65536) Vl[65536,81920)
#define STAGE_ 81920
#define ATT2_SMEM (2*STAGE_)   // 163840
#define KLOG2E 0.104117565f    // (1/sqrt(192)) * log2(e)

__device__ __forceinline__ uint32_t swzK(int r, int c){  // pitch 384, 24 chunks
    return (uint32_t)(r*384 + (((c & ~7) | ((c & 7) ^ (r & 7))) << 4));
}
__device__ __forceinline__ uint32_t swzV(int r, int c){  // pitch 256, 16 chunks
    return (uint32_t)(r*256 + (((c & 8) | ((c & 7) ^ (r & 7))) << 4));
}

__device__ __forceinline__ void att_load_kv(uint32_t dst,
    const __nv_bfloat16* kh, const __nv_bfloat16* kl,
    const __nv_bfloat16* vh, const __nv_bfloat16* vl, int kb)
{
    const int tid = threadIdx.x;
#pragma unroll
    for (int p = 0; p < 6; p++){
        int i = tid + p*256;          // 1536 K chunks
        int r = i / 24, c = i - r*24;
        uint32_t so = swzK(r, c);
        const char* sh = (const char*)(kh + (size_t)(kb + r)*192) + c*16;
        const char* sl = (const char*)(kl + (size_t)(kb + r)*192) + c*16;
        cpa16(dst + so,         sh, 16);
        cpa16(dst + 24576 + so, sl, 16);
    }
#pragma unroll
    for (int p = 0; p < 4; p++){
        int i = tid + p*256;          // 1024 V chunks
        int r = i >> 4, c = i & 15;
        uint32_t so = swzV(r, c);
        const char* sh = (const char*)(vh + (size_t)(kb + r)*128) + c*16;
        const char* sl = (const char*)(vl + (size_t)(kb + r)*128) + c*16;
        cpa16(dst + 49152 + so, sh, 16);
        cpa16(dst + 65536 + so, sl, 16);
    }
}

__global__ void __launch_bounds__(256, 1) k_attn2()
{
    extern __shared__ char sm[];
    uint32_t sb = smem_u32(sm);
    const int tid = threadIdx.x, wid = tid >> 5, lane = tid & 31;
    const int bh = blockIdx.y;
    const int b  = bh >> 4, h = bh & 15;
    const int qi = gridDim.x - 1 - blockIdx.x;   // heavy tiles first
    const int qb = qi * 128;
    const int nt = 2*qi + 2;

    const __nv_bfloat16* gqh = g_qh + ((size_t)bh * S_ + qb) * 192;
    const __nv_bfloat16* gql = g_ql + ((size_t)bh * S_ + qb) * 192;
    const __nv_bfloat16* gkh = g_kh + (size_t)bh * S_ * 192;
    const __nv_bfloat16* gkl = g_kl + (size_t)bh * S_ * 192;
    const __nv_bfloat16* gvh = g_vh + (size_t)bh * S_ * 128;
    const __nv_bfloat16* gvl = g_vl + (size_t)bh * S_ * 128;

    // ---- stage Q (128 x 192 hi+lo) through smem into registers
#pragma unroll
    for (int p = 0; p < 12; p++){
        int i = tid + p*256;          // 3072 chunks
        int r = i / 24, c = i - r*24;
        uint32_t so = swzK(r, c);
        cpa16(sb + so,         (const char*)gqh + (size_t)r*384 + c*16, 16);
        cpa16(sb + 49152 + so, (const char*)gql + (size_t)r*384 + c*16, 16);
    }
    CP_COMMIT(); CP_WAIT0();
    __syncthreads();

    uint32_t qh[12][4], ql[12][4];
    {
        int row = wid*16 + (lane & 15);
#pragma unroll
        for (int kc = 0; kc < 12; kc++){
            int c = 2*kc + (lane >> 4);
            uint32_t so = swzK(row, c);
            ldsm4(qh[kc], sb + so);
            ldsm4(ql[kc], sb + 49152 + so);
        }
    }
    __syncthreads();

    float oacc[16][4];
#pragma unroll
    for (int n = 0; n < 16; n++)
#pragma unroll
        for (int c = 0; c < 4; c++) oacc[n][c] = 0.f;
    float m0 = -CUDART_INF_F, m1 = -CUDART_INF_F, l0 = 0.f, l1 = 0.f;

    const int qr0 = qb + wid*16 + (lane >> 2);
    const int koff = 2*(lane & 3);

    att_load_kv(sb, gkh, gkl, gvh, gvl, 0);
    CP_COMMIT();

    for (int t = 0; t < nt; t++){
        if (t + 1 < nt){
            att_load_kv(sb + ((t+1)&1)*STAGE_, gkh, gkl, gvh, gvl, (t+1)*64);
            CP_COMMIT(); CP_WAIT1();
        } else {
            CP_WAIT0();
        }
        __syncthreads();

        uint32_t kbse = sb + (t & 1) * STAGE_;

        // ---- scores: 16 x 64 per warp
        float sacc[8][4];
#pragma unroll
        for (int j = 0; j < 8; j++)
#pragma unroll
            for (int c = 0; c < 4; c++) sacc[j][c] = 0.f;

#pragma unroll
        for (int kc = 0; kc < 12; kc++){
#pragma unroll
            for (int g = 0; g < 4; g++){
                int rowb = g*16 + ((lane >> 4) << 3) + (lane & 7);
                int c = 2*kc + ((lane >> 3) & 1);
                uint32_t so = swzK(rowb, c);
                uint32_t kh4[4], kl4[4];
                ldsm4(kh4, kbse + so);
                ldsm4(kl4, kbse + 24576 + so);
                mma16816(sacc[2*g],   qh[kc], kh4[0], kh4[1]);
                mma16816(sacc[2*g+1], qh[kc], kh4[2], kh4[3]);
                mma16816(sacc[2*g],   ql[kc], kh4[0], kh4[1]);
                mma16816(sacc[2*g+1], ql[kc], kh4[2], kh4[3]);
                mma16816(sacc[2*g],   qh[kc], kl4[0], kl4[1]);
                mma16816(sacc[2*g+1], qh[kc], kl4[2], kl4[3]);
            }
        }

        // ---- causal mask (only near-diagonal tiles)
        const int kb = t*64;
        if (kb + 63 > qr0){
#pragma unroll
            for (int j = 0; j < 8; j++){
                if (kb + koff + 8*j     > qr0) sacc[j][0] = -CUDART_INF_F;
                if (kb + koff + 8*j + 1 > qr0) sacc[j][1] = -CUDART_INF_F;
            }
        }
        if (kb + 63 > qr0 + 8){
#pragma unroll
            for (int j = 0; j < 8; j++){
                if (kb + koff + 8*j     > qr0 + 8) sacc[j][2] = -CUDART_INF_F;
                if (kb + koff + 8*j + 1 > qr0 + 8) sacc[j][3] = -CUDART_INF_F;
            }
        }

        // ---- online softmax (4 lanes per row)
        float mt0 = -CUDART_INF_F, mt1 = -CUDART_INF_F;
#pragma unroll
        for (int j = 0; j < 8; j++){
            mt0 = fmaxf(mt0, fmaxf(sacc[j][0], sacc[j][1]));
            mt1 = fmaxf(mt1, fmaxf(sacc[j][2], sacc[j][3]));
        }
        mt0 = fmaxf(mt0, __shfl_xor_sync(0xffffffffu, mt0, 1));
        mt0 = fmaxf(mt0, __shfl_xor_sync(0xffffffffu, mt0, 2));
        mt1 = fmaxf(mt1, __shfl_xor_sync(0xffffffffu, mt1, 1));
        mt1 = fmaxf(mt1, __shfl_xor_sync(0xffffffffu, mt1, 2));
        float nm0 = fmaxf(m0, mt0), nm1 = fmaxf(m1, mt1);
        float f0 = ex2f((m0 - nm0) * KLOG2E);
        float f1 = ex2f((m1 - nm1) * KLOG2E);
        float ps0 = 0.f, ps1 = 0.f;
#pragma unroll
        for (int j = 0; j < 8; j++){
            sacc[j][0] = ex2f((sacc[j][0] - nm0) * KLOG2E); ps0 += sacc[j][0];
            sacc[j][1] = ex2f((sacc[j][1] - nm0) * KLOG2E); ps0 += sacc[j][1];
            sacc[j][2] = ex2f((sacc[j][2] - nm1) * KLOG2E); ps1 += sacc[j][2];
            sacc[j][3] = ex2f((sacc[j][3] - nm1) * KLOG2E); ps1 += sacc[j][3];
        }
        ps0 += __shfl_xor_sync(0xffffffffu, ps0, 1);
        ps0 += __shfl_xor_sync(0xffffffffu, ps0, 2);
        ps1 += __shfl_xor_sync(0xffffffffu, ps1, 1);
        ps1 += __shfl_xor_sync(0xffffffffu, ps1, 2);
        l0 = l0*f0 + ps0; l1 = l1*f1 + ps1;
        m0 = nm0; m1 = nm1;

        // rescale O
#pragma unroll
        for (int n = 0; n < 16; n++){
            oacc[n][0] *= f0; oacc[n][1] *= f0;
            oacc[n][2] *= f1; oacc[n][3] *= f1;
        }

        // pack P into A fragments (hi/lo)
        uint32_t ph[4][4], pl[4][4];
#pragma unroll
        for (int tt = 0; tt < 4; tt++){
            pksplit(sacc[2*tt][0],   sacc[2*tt][1],   ph[tt][0], pl[tt][0]);
            pksplit(sacc[2*tt][2],   sacc[2*tt][3],   ph[tt][1], pl[tt][1]);
            pksplit(sacc[2*tt+1][0], sacc[2*tt+1][1], ph[tt][2], pl[tt][2]);
            pksplit(sacc[2*tt+1][2], sacc[2*tt+1][3], ph[tt][3], pl[tt][3]);
        }

        // ---- PV accumulate
#pragma unroll
        for (int tt = 0; tt < 4; tt++){
            int rowv = tt*16 + ((lane & 7) | (((lane >> 3) & 1) << 3));
#pragma unroll
            for (int g = 0; g < 8; g++){
                int c = 2*g + (lane >> 4);
                uint32_t so = swzV(rowv, c);
                uint32_t vh4[4], vl4[4];
                ldsm4t(vh4, kbse + 49152 + so);
                ldsm4t(vl4, kbse + 65536 + so);
                mma16816(oacc[2*g],   ph[tt], vh4[0], vh4[1]);
                mma16816(oacc[2*g+1], ph[tt], vh4[2], vh4[3]);
                mma16816(oacc[2*g],   pl[tt], vh4[0], vh4[1]);
                mma16816(oacc[2*g+1], pl[tt], vh4[2], vh4[3]);
                mma16816(oacc[2*g],   ph[tt], vl4[0], vl4[1]);
                mma16816(oacc[2*g+1], ph[tt], vl4[2], vl4[3]);
            }
        }
        __syncthreads();
    }

    // ---- epilogue: normalize, split hi/lo, store
    float il0 = 1.0f / l0, il1 = 1.0f / l1;
    const int r0 = qb + wid*16 + (lane >> 2);
    size_t ro0 = (size_t)(b*S_ + r0) * NO_ + h*128;
    size_t ro1 = (size_t)(b*S_ + r0 + 8) * NO_ + h*128;
#pragma unroll
    for (int n = 0; n < 16; n++){
        int col = n*8 + 2*(lane & 3);
        uint32_t hi, lo;
        pksplit(oacc[n][0]*il0, oacc[n][1]*il0, hi, lo);
        *(uint32_t*)(g_ath + ro0 + col) = hi;
        *(uint32_t*)(g_atl + ro0 + col) = lo;
        pksplit(oacc[n][2]*il1, oacc[n][3]*il1, hi, lo);
        *(uint32_t*)(g_ath + ro1 + col) = hi;
        *(uint32_t*)(g_atl + ro1 + col) = lo;
    }
}

// ---------------- launch ----------------
static void* sym_addr(const void* s) { void* p = nullptr; cudaGetSymbolAddress(&p, s); return p; }

extern "C" void kernel_launch(void* const* d_in, const int* in_sizes, int n_in,
                              void* d_out, int out_size)
{
    const float* x   = (const float*)d_in[0];
    const float* fc  = (const float*)d_in[2];
    const float* wq  = (const float*)d_in[4];
    const float* wa  = (const float*)d_in[5];
    const float* wb  = (const float*)d_in[6];
    const float* wo  = (const float*)d_in[7];
    const float* knw = (const float*)d_in[8];
    float* out = (float*)d_out;

    cudaFuncSetAttribute(k_mmagemm, cudaFuncAttributeMaxDynamicSharedMemorySize, GEMM_SMEM);
    cudaFuncSetAttribute(k_attn2,   cudaFuncAttributeMaxDynamicSharedMemorySize, ATT2_SMEM);

    __nv_bfloat16 *xh  = (__nv_bfloat16*)sym_addr(g_xh),  *xl  = (__nv_bfloat16*)sym_addr(g_xl);
    __nv_bfloat16 *wqh = (__nv_bfloat16*)sym_addr(g_wqh), *wql = (__nv_bfloat16*)sym_addr(g_wql);
    __nv_bfloat16 *wah = (__nv_bfloat16*)sym_addr(g_wah), *wal = (__nv_bfloat16*)sym_addr(g_wal);
    __nv_bfloat16 *wbh = (__nv_bfloat16*)sym_addr(g_wbh), *wbl = (__nv_bfloat16*)sym_addr(g_wbl);
    __nv_bfloat16 *woh = (__nv_bfloat16*)sym_addr(g_woh), *wol = (__nv_bfloat16*)sym_addr(g_wol);
    __nv_bfloat16 *kvh = (__nv_bfloat16*)sym_addr(g_kvnh),*kvl = (__nv_bfloat16*)sym_addr(g_kvnl);
    __nv_bfloat16 *ath = (__nv_bfloat16*)sym_addr(g_ath), *atl = (__nv_bfloat16*)sym_addr(g_atl);
    float *qf  = (float*)sym_addr(g_q);
    float *kvf = (float*)sym_addr(g_kv);

    dim3 t(256);
    k_cvt<<<(M_*DIM_)/1024,   t>>>(x,  xh,  xl,  M_*DIM_);
    k_cvt<<<(NQ_*DIM_)/1024,  t>>>(wq, wqh, wql, NQ_*DIM_);
    k_cvt<<<(NKV_*DIM_)/1024, t>>>(wa, wah, wal, NKV_*DIM_);
    k_cvt<<<(NUP_*RANK_)/1024,t>>>(wb, wbh, wbl, NUP_*RANK_);
    k_cvt<<<(DIM_*NO_)/1024,  t>>>(wo, woh, wol, DIM_*NO_);

    // q = x @ wq^T
    k_mmagemm<<<dim3(NQ_/128, M_/128), t, GEMM_SMEM>>>(xh, xl, wqh, wql, qf, M_, NQ_, DIM_);
    // kv = x @ wkv_a^T
    k_mmagemm<<<dim3((NKV_+127)/128, M_/128), t, GEMM_SMEM>>>(xh, xl, wah, wal, kvf, M_, NKV_, DIM_);
    // rmsnorm + ropes
    k_ew<<<M_, 256>>>(fc, knw);
    // kv_up = kvn @ wkv_b^T
    k_mmagemm<<<dim3(NUP_/128, M_/128), t, GEMM_SMEM>>>(kvh, kvl, wbh, wbl,
                                                        (float*)sym_addr(g_kvup), M_, NUP_, RANK_);
    // head-major bf16 hi/lo Q/K/V
    k_qkvcvt<<<M_, 256>>>();
    // HMMA flash attention
    k_attn2<<<dim3(S_/128, B_*NH_), t, ATT2_SMEM>>>();
    // out = attn @ wo^T
    k_mmagemm<<<dim3(DIM_/128, M_/128), t, GEMM_SMEM>>>(ath, atl, woh, wol, out, M_, DIM_, NO_);
}